// round 6
// baseline (speedup 1.0000x reference)
#include <cuda_runtime.h>

// Problem constants (fixed by the reference)
#define NN        64
#define INV_DX    63.0f                 // 1/DX, DX = 1/(64-1)
#define DXC       (1.0f/63.0f)
#define E_OUT_C   80.0f                 // E_IN = 1
#define FOUR_PI_F 12.566370614359172f
#define EPSF      1.1920928955078125e-07f
#define EPSF2     (EPSF*EPSF)
#define TPB       512
#define WPB       16                    // warps per block, 1 point per warp
#define MAXQ      512

__device__ float    g_accum = 0.0f;
__device__ unsigned g_count = 0;

template<int NQC>   // NQC > 0: compile-time charge count; NQC == 0: runtime nq
__global__ __launch_bounds__(TPB)
void boundary_loss_fused(const float* __restrict__ outf,    // (2,1,64,64,64)
                         const float* __restrict__ q,      // (NQ)
                         const float* __restrict__ xq,     // (NQ,3)
                         const int*   __restrict__ xi,
                         const int*   __restrict__ yi,
                         const int*   __restrict__ zi,
                         const float* __restrict__ normals,// (NB,3)
                         float* __restrict__ outp,
                         int nb, int nq_rt)
{
    const int nq = (NQC > 0) ? NQC : nq_rt;

    __shared__ float4 s4[MAXQ];         // {x, y, z, q} per charge
    __shared__ float  warp_acc[WPB];

    int tid  = threadIdx.x;
    int wid  = tid >> 5;
    int lane = tid & 31;

    // stage charges packed as float4 (issued first; latency overlapped below)
    for (int j = tid; j < nq; j += TPB) {
        float4 v;
        v.x = xq[3*j + 0];
        v.y = xq[3*j + 1];
        v.z = xq[3*j + 2];
        v.w = q[j];
        s4[j] = v;
    }

    int i = blockIdx.x * WPB + wid;     // boundary-point index for this warp
    float acc = 0.0f;
    bool active = (i < nb);

    // ---- everything independent of staged charges: issue BEFORE the barrier ----
    int x = 0, y = 0, z = 0;
    float nx = 0.f, ny = 0.f, nz = 0.f;
    float c0a=0,c0b=0,lfa=0,lfb=0,rta=0,rtb=0,bla=0,blb=0,aba=0,abb=0,bka=0,bkb=0,fra=0,frb=0;
    if (active) {
        x  = xi[i]; y = yi[i]; z = zi[i];
        nx = normals[3*i + 0]; ny = normals[3*i + 1]; nz = normals[3*i + 2];
        long base = ((long)x * NN + y) * NN + z;
        const float* ob0 = outf;
        const float* ob1 = outf + (long)NN * NN * NN;
        c0a = ob0[base];        c0b = ob1[base];
        lfa = ob0[base-NN*NN];  lfb = ob1[base-NN*NN];
        rta = ob0[base+NN*NN];  rtb = ob1[base+NN*NN];
        bla = ob0[base-NN];     blb = ob1[base-NN];
        aba = ob0[base+NN];     abb = ob1[base+NN];
        bka = ob0[base-1];      bkb = ob1[base-1];
        fra = ob0[base+1];      frb = ob1[base+1];
    }
    __syncthreads();

    if (active) {
        float px = x * DXC, py = y * DXC, pz = z * DXC;

        // ---- branchless charge loop, lanes strided by 32 ----
        // r==0 semantics: clamp r2 to EPS^2 -> 1/r == 1/EPS (matches ref);
        // grad term is c*dr with dr==0 -> 0 (matches ref).
        float gsum = 0.0f, gnd = 0.0f;
        #pragma unroll
        for (int k = 0; k < (NQC > 0 ? (NQC + 31) / 32 : 1); k++) {
            if (NQC > 0) {
                int j = lane + 32 * k;
                if (j < NQC) {
                    float4 v = s4[j];
                    float dx = px - v.x, dy = py - v.y, dz = pz - v.z;
                    float r2 = fmaf(dx, dx, fmaf(dy, dy, dz * dz));
                    r2 = fmaxf(r2, EPSF2);
                    float rinv = rsqrtf(r2);
                    float qr   = v.w * rinv;
                    gsum += qr;
                    float c = qr * rinv * rinv;
                    float dot = fmaf(dx, nx, fmaf(dy, ny, dz * nz));
                    gnd = fmaf(-c, dot, gnd);
                }
            } else {
                for (int j = lane; j < nq; j += 32) {
                    float4 v = s4[j];
                    float dx = px - v.x, dy = py - v.y, dz = pz - v.z;
                    float r2 = fmaf(dx, dx, fmaf(dy, dy, dz * dz));
                    r2 = fmaxf(r2, EPSF2);
                    float rinv = rsqrtf(r2);
                    float qr   = v.w * rinv;
                    gsum += qr;
                    float c = qr * rinv * rinv;
                    float dot = fmaf(dx, nx, fmaf(dy, ny, dz * nz));
                    gnd = fmaf(-c, dot, gnd);
                }
            }
        }

        // warp butterfly reduction: 2 values
        #pragma unroll
        for (int s = 16; s > 0; s >>= 1) {
            gsum += __shfl_xor_sync(0xffffffffu, gsum, s);
            gnd  += __shfl_xor_sync(0xffffffffu, gnd,  s);
        }

        const float inv4pi = 1.0f / FOUR_PI_F;
        float g    = gsum * inv4pi;
        float gcnd = gnd  * inv4pi;

        acc = g * g;    // loss1 (batch-invariant)

        // loss2: finite differences, both batches
        float gxinA  = (nx > 0.0f) ? (c0a - lfa) : (rta - c0a);
        float gxoutA = (nx > 0.0f) ? (rta - c0a) : (c0a - lfa);
        float gyinA  = (ny > 0.0f) ? (c0a - bla) : (aba - c0a);
        float gyoutA = (ny > 0.0f) ? (aba - c0a) : (c0a - bla);
        float gzinA  = (nz > 0.0f) ? (c0a - bka) : (fra - c0a);
        float gzoutA = (nz > 0.0f) ? (fra - c0a) : (c0a - bka);
        float ndinA  = (gxinA *nx + gyinA *ny + gzinA *nz) * INV_DX;
        float ndoutA = (gxoutA*nx + gyoutA*ny + gzoutA*nz) * INV_DX;
        float tA = (ndinA + gcnd) - E_OUT_C * ndoutA;

        float gxinB  = (nx > 0.0f) ? (c0b - lfb) : (rtb - c0b);
        float gxoutB = (nx > 0.0f) ? (rtb - c0b) : (c0b - lfb);
        float gyinB  = (ny > 0.0f) ? (c0b - blb) : (abb - c0b);
        float gyoutB = (ny > 0.0f) ? (abb - c0b) : (c0b - blb);
        float gzinB  = (nz > 0.0f) ? (c0b - bkb) : (frb - c0b);
        float gzoutB = (nz > 0.0f) ? (frb - c0b) : (c0b - bkb);
        float ndinB  = (gxinB *nx + gyinB *ny + gzinB *nz) * INV_DX;
        float ndoutB = (gxoutB*nx + gyoutB*ny + gzoutB*nz) * INV_DX;
        float tB = (ndinB + gcnd) - E_OUT_C * ndoutB;

        acc += 0.5f * (tA * tA + tB * tB);    // 1/BATCH
    }

    // ---- block reduction: one value per warp ----
    if (lane == 0) warp_acc[wid] = acc;
    __syncthreads();

    if (tid == 0) {
        float bsum = 0.0f;
        #pragma unroll
        for (int w = 0; w < WPB; w++) bsum += warp_acc[w];
        atomicAdd(&g_accum, bsum);
        __threadfence();
        unsigned old = atomicAdd(&g_count, 1u);
        if (old == gridDim.x - 1) {           // last block: finalize + reset
            float total = *(volatile float*)&g_accum;
            outp[0] = total / (float)nb;
            g_accum = 0.0f;
            __threadfence();
            g_count = 0;
        }
    }
}

extern "C" void kernel_launch(void* const* d_in, const int* in_sizes, int n_in,
                              void* d_out, int out_size)
{
    // metadata order: output, q, xq, points, x_idx, y_idx, z_idx, normals
    const float* outf    = (const float*)d_in[0];
    const float* q       = (const float*)d_in[1];
    const float* xq      = (const float*)d_in[2];
    const int*   xi      = (const int*)  d_in[4];
    const int*   yi      = (const int*)  d_in[5];
    const int*   zi      = (const int*)  d_in[6];
    const float* normals = (const float*)d_in[7];

    int nq = in_sizes[1];
    int nb = in_sizes[4];

    int blocks = (nb + WPB - 1) / WPB;

    if (nq == 200) {
        boundary_loss_fused<200><<<blocks, TPB>>>(outf, q, xq, xi, yi, zi, normals,
                                                  (float*)d_out, nb, nq);
    } else {
        boundary_loss_fused<0><<<blocks, TPB>>>(outf, q, xq, xi, yi, zi, normals,
                                                (float*)d_out, nb, nq);
    }
}